// round 16
// baseline (speedup 1.0000x reference)
#include <cuda_runtime.h>
#include <cuda_bf16.h>

#define BB 256
#define TT 512
#define LL 40
#define NCF 22

// Scratch (allocation-free: __device__ globals)
__device__ float g_X[BB * TT * 32];  // per (b,t): [0..7]=emb-sum, [8..29]=cont, [30]=0 (vfb slot), [31]=0
__device__ float g_S[BB * TT * 8];   // per (b,t): {ccl, d, td*24, mask_prev, lb_prev, 0,0,0}

typedef unsigned long long u64;

__device__ __forceinline__ u64 pack2(float x, float y) {
    u64 r; asm("mov.b64 %0, {%1, %2};" : "=l"(r) : "f"(x), "f"(y)); return r;
}
__device__ __forceinline__ float2 unpack2(u64 v) {
    float2 r; asm("mov.b64 {%0, %1}, %2;" : "=f"(r.x), "=f"(r.y) : "l"(v)); return r;
}
__device__ __forceinline__ void ffma2(u64& d, u64 a, u64 b) {
    asm("fma.rn.f32x2 %0, %1, %2, %0;" : "+l"(d) : "l"(a), "l"(b));
}
__device__ __forceinline__ float sqrt_approx(float x) {
    float r; asm("sqrt.approx.f32 %0, %1;" : "=f"(r) : "f"(x)); return r;
}
__device__ __forceinline__ float tanh_approx(float x) {
    float r; asm("tanh.approx.f32 %0, %1;" : "=f"(r) : "f"(x)); return r;
}

// ---------------------------------------------------------------------------
// Kernel 1: warp-cooperative embedding gather + feature staging + scalars.
// One WARP per (b,t): 8 lanes share each emb row (consecutive 32B -> 1
// wavefront per row instead of 8). 4 rows gathered per pass, 10 passes.
// ---------------------------------------------------------------------------
__global__ void precompute_kernel(
    const float* __restrict__ cont, const int* __restrict__ cat,
    const float* __restrict__ lb, const int* __restrict__ mask,
    const float* __restrict__ dvec, const float* __restrict__ td,
    const float* __restrict__ emb)
{
    const int lane = threadIdx.x & 31;
    const int bt = blockIdx.x * (blockDim.x >> 5) + (threadIdx.x >> 5);
    const int b = bt >> 9;            // T = 512
    const int t = bt & (TT - 1);

    // Lane-parallel load of the 40 cat indices for this (b,t)
    const int* cp = cat + (size_t)bt * LL;
    int c1 = __ldg(cp + lane);                          // cats 0..31
    int c2 = (lane < 8) ? __ldg(cp + 32 + lane) : 0;    // cats 32..39

    const int r   = lane >> 3;   // row-group 0..3
    const int col = lane & 7;    // emb column 0..7

    float acc = 0.0f;
#pragma unroll
    for (int p = 0; p < 10; p++) {
        int idx;
        if (p < 8) idx = __shfl_sync(0xffffffffu, c1, p * 4 + r);
        else       idx = __shfl_sync(0xffffffffu, c2, (p - 8) * 4 + r);
        acc += __ldg(emb + (size_t)idx * 8 + col);
    }
    // Combine the 4 row-groups (lanes l, l+8, l+16, l+24 hold same col)
    acc += __shfl_xor_sync(0xffffffffu, acc, 8);
    acc += __shfl_xor_sync(0xffffffffu, acc, 16);

    float* xo = g_X + (size_t)bt * 32;
    const float* cr = cont + (size_t)bt * NCF;
    if (lane < 8)   xo[lane] = acc;
    if (lane < NCF) xo[8 + lane] = __ldg(cr + lane);
    if (lane == 22) xo[30] = 0.0f;
    if (lane == 23) xo[31] = 0.0f;

    // Gender count from the t=0 cat row of this batch (ballot/popc)
    const int b00 = b * TT;
    const int* c0p = cat + (size_t)b00 * LL;
    int g1 = __ldg(c0p + lane);
    unsigned bal1 = __ballot_sync(0xffffffffu, g1 == 5);
    int g2 = (lane < 8) ? __ldg(c0p + 32 + lane) : 0;
    unsigned bal2 = __ballot_sync(0xffffffffu, (lane < 8) && (g2 == 5));
    int gc = __popc(bal1) + __popc(bal2);

    if (lane == 0) {
        float age = __ldg(cont + (size_t)b00 * NCF + 2) * 16.936469f + 58.239251f;
        float wgt = __ldg(cont + (size_t)b00 * NCF + 21) * 30.519849f + 87.5752f;
        float gender = (float)gc * 0.15f + 0.85f;
        float creat = __ldg(cr + 11) * 1.418099f + 1.314668f;
        float cc = (140.0f - age) * wgt * gender / (72.0f * creat);

        float mp = 0.0f, lp = 0.0f;
        if (t > 0) { mp = (float)__ldg(mask + bt - 1); lp = __ldg(lb + bt - 1); }

        float* so = g_S + (size_t)bt * 8;
        so[0] = cc;
        so[1] = __ldg(dvec + bt);
        so[2] = __ldg(td + bt) * 24.0f;
        so[3] = mp;
        so[4] = lp;
    }
}

// ---------------------------------------------------------------------------
// Kernel 2: pipelined GRU + PK recurrence (R12 schedule, 2 barriers/step).
// 128 blocks (<=1/SM), 256 threads (8 warps), 2 batch elements per block:
//   tid 0..191  : GEMV workers (k-packed f32x2 weight row in regs, both
//                 batches). Overlap phase: do_acc(t+1) THEN publish(t+1).
//   warps 0-3   : also run the gate math (tanh.approx) in the G phase;
//                 vfb weights (w30) held in REGISTERS (no smem load).
//   warp 6 / 7  : x staging + PK-scalar register preload (G phase) +
//                 eta reduction + shortened PK chain (OV) for batch 0 / 1.
// Per step: S1 | G: gates + x STS/LDG + srow preload | S2 | OV: acc+publish // eta+PK.
// ---------------------------------------------------------------------------
__global__ void __launch_bounds__(256, 1) rnn_kernel(
    const float* __restrict__ Wih, const float* __restrict__ Whh,
    const float* __restrict__ bih, const float* __restrict__ bhh,
    const float* __restrict__ Wout, const float* __restrict__ bout,
    float* __restrict__ out)
{
    __shared__ __align__(16) float x_sh[2][32];
    __shared__ __align__(16) float h_sh[2][64];
    __shared__ float gsum_sh[2][128];   // r rows 0-63, z rows 64-127 (gi+gh fused)
    __shared__ float gin_sh[2][64];     // n rows: gi part
    __shared__ float ghn_sh[2][64];     // n rows: gh part
    __shared__ float vfb_sh[2];
    __shared__ __align__(16) float s_sh[2][TT * 8];  // 32 KB: all PK scalars

    const int tid  = threadIdx.x;
    const int lane = tid & 31;
    const int wid  = tid >> 5;
    const int b0   = blockIdx.x * 2;

    // ---- One-time preload of g_S rows for both batches (contiguous 8192 f) ----
    {
        const float4* src = reinterpret_cast<const float4*>(g_S + (size_t)b0 * TT * 8);
        float4* dst = reinterpret_cast<float4*>(&s_sh[0][0]);
#pragma unroll
        for (int j = 0; j < 8; j++)
            dst[tid + 256 * j] = __ldg(src + tid + 256 * j);
    }

    // Per-thread weights (k-packed pairs)
    u64 wihq[16], whhq[32];
    float bi = 0.0f, bh = 0.0f;
    float wo[8], bo[4];
    float w30r = 0.0f, w30z = 0.0f, w30n = 0.0f;   // gate-thread vfb weights (regs)

    if (tid < 192) {
        float tw[32];
#pragma unroll
        for (int k = 0; k < 31; k++) tw[k] = __ldg(Wih + tid * 31 + k);
        tw[30] = 0.0f;   // vfb column handled by gates via registers
        tw[31] = 0.0f;
#pragma unroll
        for (int p = 0; p < 16; p++) wihq[p] = pack2(tw[2 * p], tw[2 * p + 1]);
        float th[64];
#pragma unroll
        for (int k = 0; k < 64; k++) th[k] = __ldg(Whh + tid * 64 + k);
#pragma unroll
        for (int p = 0; p < 32; p++) whhq[p] = pack2(th[2 * p], th[2 * p + 1]);
        bi = __ldg(bih + tid);
        bh = __ldg(bhh + tid);
        if (tid < 128) {
            int i = tid & 63;
            w30r = __ldg(Wih + (i)       * 31 + 30);
            w30z = __ldg(Wih + (64 + i)  * 31 + 30);
            w30n = __ldg(Wih + (128 + i) * 31 + 30);
        }
    } else {
#pragma unroll
        for (int o = 0; o < 4; o++) {
            wo[2 * o]     = __ldg(Wout + o * 64 + lane);
            wo[2 * o + 1] = __ldg(Wout + o * 64 + 32 + lane);
            bo[o] = __ldg(bout + o);
        }
    }

    // GEMV accumulators for both batches
    u64 AX0[2], AX1[2], AH0[2], AH1[2], AH2[2], AH3[2];

    auto do_acc = [&]() {
#pragma unroll
        for (int m = 0; m < 2; m++) {
            u64 a0 = 0ull, a1 = 0ull, c0 = 0ull, c1 = 0ull, c2 = 0ull, c3 = 0ull;
            const ulonglong2* xq = reinterpret_cast<const ulonglong2*>(&x_sh[m][0]);
#pragma unroll
            for (int c = 0; c < 8; c++) {
                ulonglong2 v = xq[c];
                ffma2(a0, wihq[2 * c],     v.x);
                ffma2(a1, wihq[2 * c + 1], v.y);
            }
            const ulonglong2* hq = reinterpret_cast<const ulonglong2*>(&h_sh[m][0]);
#pragma unroll
            for (int c = 0; c < 16; c += 4) {
                ulonglong2 v0 = hq[c], v1 = hq[c + 1], v2 = hq[c + 2], v3 = hq[c + 3];
                ffma2(c0, whhq[2 * c],     v0.x);
                ffma2(c0, whhq[2 * c + 1], v0.y);
                ffma2(c1, whhq[2 * c + 2], v1.x);
                ffma2(c1, whhq[2 * c + 3], v1.y);
                ffma2(c2, whhq[2 * c + 4], v2.x);
                ffma2(c2, whhq[2 * c + 5], v2.y);
                ffma2(c3, whhq[2 * c + 6], v3.x);
                ffma2(c3, whhq[2 * c + 7], v3.y);
            }
            AX0[m] = a0; AX1[m] = a1;
            AH0[m] = c0; AH1[m] = c1; AH2[m] = c2; AH3[m] = c3;
        }
    };
    auto publish = [&]() {
#pragma unroll
        for (int m = 0; m < 2; m++) {
            float2 u0 = unpack2(AX0[m]), u1 = unpack2(AX1[m]);
            float xs = ((u0.x + u0.y) + (u1.x + u1.y)) + bi;
            float2 h0 = unpack2(AH0[m]), h1 = unpack2(AH1[m]);
            float2 h2 = unpack2(AH2[m]), h3 = unpack2(AH3[m]);
            float hs = ((h0.x + h0.y) + (h1.x + h1.y)) +
                       ((h2.x + h2.y) + (h3.x + h3.y)) + bh;
            if (tid < 128) gsum_sh[m][tid] = xs + hs;
            else { gin_sh[m][tid - 128] = xs; ghn_sh[m][tid - 128] = hs; }
        }
    };

    // PK carry + x-prefetch register + PK-scalar regs (live only in PK warps)
    float Cv = 0.0f, Dv = 0.0f;
    float4 xreg = make_float4(0.f, 0.f, 0.f, 0.f);
    float cc = 0.f, dd = 0.f, ttau = 0.f, mp = 0.f, lp = 0.f;
    const int pk_m = wid - 6;
    const bool is_pk_ld = (wid >= 6) && (lane < 8);
    const float4* xsrc = reinterpret_cast<const float4*>(
        g_X + ((size_t)(b0 + (wid >= 6 ? pk_m : 0)) * TT) * 32);

    // ---- Prime: zero h/vfb, x(0) -> smem, x(1) -> PK regs ----
    if (tid < 128) h_sh[tid >> 6][tid & 63] = 0.0f;
    if (tid < 2) vfb_sh[tid] = 0.0f;
    if (tid >= 128 && tid < 144) {
        int j = tid - 128, m = j >> 3, c = j & 7;
        reinterpret_cast<float4*>(&x_sh[m][0])[c] =
            reinterpret_cast<const float4*>(g_X + ((size_t)(b0 + m) * TT) * 32)[c];
    }
    if (is_pk_ld) xreg = __ldg(xsrc + 8 + lane);   // x(1)
    __syncthreads();
    if (tid < 192) { do_acc(); publish(); }        // step-0 sums (h part = 0)

#pragma unroll 1
    for (int t = 0; t < TT; ++t) {
        __syncthreads();  // S1: gsum(t), vfb(t) visible; x_sh reads of OV(t-1) done

        // ---- G: gates(t) on warps 0-3 || x staging + srow preload on PK warps ----
        if (tid < 128) {
            int m = tid >> 6, i = tid & 63;
            float vfb = vfb_sh[m];
            float gr = fmaf(w30r, vfb, gsum_sh[m][i]);
            float gz = fmaf(w30z, vfb, gsum_sh[m][64 + i]);
            float r  = fmaf(tanh_approx(0.5f * gr), 0.5f, 0.5f);   // sigmoid
            float z  = fmaf(tanh_approx(0.5f * gz), 0.5f, 0.5f);
            float gn = fmaf(w30n, vfb, gin_sh[m][i]) + r * ghn_sh[m][i];
            float n  = tanh_approx(gn);
            float ho = h_sh[m][i];
            h_sh[m][i] = fmaf(z, ho - n, n);
        } else if (wid >= 6) {
            if (is_pk_ld) {
                if ((t + 1) < TT)
                    reinterpret_cast<float4*>(&x_sh[pk_m][0])[lane] = xreg;  // x(t+1)
                int tn = (t + 2) < TT ? (t + 2) : (TT - 1);
                xreg = __ldg(xsrc + (size_t)tn * 8 + lane);                  // x(t+2)
            }
            // Preload PK scalars for step t into registers (slack-side LDS)
            const float* srow = &s_sh[pk_m][t * 8];
            cc = srow[0]; dd = srow[1]; ttau = srow[2];
            mp = srow[8 + 3]; lp = srow[8 + 4];
        }
        __syncthreads();  // S2: h(t), x(t+1) visible

        // ---- OV: do_acc(t+1)+publish(t+1) (workers) || eta+PK(t) (w6/7) ----
        if (tid < 192) {
            if ((t + 1) < TT) { do_acc(); publish(); }
        } else {
            int m = pk_m;
            float hl = h_sh[m][lane], hh2 = h_sh[m][lane + 32];
            float p0 = fmaf(wo[0], hl, wo[1] * hh2);
            float p1 = fmaf(wo[2], hl, wo[3] * hh2);
            float p2 = fmaf(wo[4], hl, wo[5] * hh2);
            float p3 = fmaf(wo[6], hl, wo[7] * hh2);
#pragma unroll
            for (int off = 16; off; off >>= 1) {
                p0 += __shfl_xor_sync(0xffffffffu, p0, off);
                p1 += __shfl_xor_sync(0xffffffffu, p1, off);
                p2 += __shfl_xor_sync(0xffffffffu, p2, off);
                p3 += __shfl_xor_sync(0xffffffffu, p3, off);
            }
            float e1 = p0 + bo[0];
            float e2 = p1 + bo[1];
            float e3 = p2 + bo[2];
            float e4 = p3 + bo[3];

            // Shortened PK chain: parallel MUFUs, analytic 1/v1 = exp(-e1)/33.1
            float Ee1  = __expf(e1);
            float Ene1 = __expf(-e1);
            float v1 = 33.1f * Ee1;
            float rcp_v1 = Ene1 * (1.0f / 33.1f);
            float k1 = 0.0396f * cc * __expf(e2);
            float R  = (-6.99f / 48.3f) * __expf(e3);
            float v2 = 48.3f * __expf(e4);
            float k2 = R * v2;
            float Rv1 = R * v1;
            float q   = k1 - k2 - Rv1;
            float delta = sqrt_approx(fmaf(q, q, 4.0f * k1 * Rv1)) * rcp_v1;
            float s  = -q * rcp_v1;
            float lam1 = (s - delta) * 0.5f;
            float lam2 = (s + delta) * 0.5f;
            float kv = k2 * rcp_v1;
            float rr_kv = (1000.0f * rcp_v1) * kv;
            float C1 =  __fdividef(rr_kv, lam1 * delta);
            float C2 = -__fdividef(rr_kv, lam2 * delta);
            float rcp_kv = __fdividef(1.0f, kv);
            float C3 = -(lam1 - R) * rcp_kv;
            float C4 = -(lam2 - R) * rcp_kv;
            float E1a = __expf(lam1 * dd), E1b = __expf(lam1 * (ttau - dd));
            float E2a = __expf(lam2 * dd), E2b = __expf(lam2 * (ttau - dd));
            float Cn = fmaf(Cv + C1, E1a, -C1) * E1b;
            float Dn = fmaf(Dv + C2, E2a, -C2) * E2b;
            float An = Cn * C3 + Dn * C4;
            Cv = Cn; Dv = Dn;

            float vfb_next = fmaf(An, 1.0f - mp, lp * mp);
            if (lane == 0) {
                if ((t + 1) < TT) vfb_sh[m] = vfb_next;   // cross-step dep first
                out[(size_t)(b0 + m) * TT + t] = An;
            }
        }
    }
}

extern "C" void kernel_launch(void* const* d_in, const int* in_sizes, int n_in,
                              void* d_out, int out_size) {
    const float* cont = (const float*)d_in[0];
    const int*   cat  = (const int*)  d_in[1];
    const float* lb   = (const float*)d_in[2];
    const int*   mask = (const int*)  d_in[3];
    const float* dvec = (const float*)d_in[4];
    const float* td   = (const float*)d_in[5];
    const float* emb  = (const float*)d_in[6];
    const float* Wih  = (const float*)d_in[7];
    const float* Whh  = (const float*)d_in[8];
    const float* bih  = (const float*)d_in[9];
    const float* bhh  = (const float*)d_in[10];
    const float* Wout = (const float*)d_in[11];
    const float* bout = (const float*)d_in[12];

    // warp-per-(b,t): 8 warps per 256-thread block -> BB*TT/8 blocks
    precompute_kernel<<<(BB * TT) / 8, 256>>>(cont, cat, lb, mask, dvec, td, emb);
    rnn_kernel<<<BB / 2, 256>>>(Wih, Whh, bih, bhh, Wout, bout, (float*)d_out);
}

// round 17
// speedup vs baseline: 1.0523x; 1.0523x over previous
#include <cuda_runtime.h>
#include <cuda_bf16.h>

#define BB 256
#define TT 512
#define LL 40
#define NCF 22

// Scratch (allocation-free: __device__ globals)
__device__ float g_X[BB * TT * 32];  // per (b,t): [0..7]=emb-sum, [8..29]=cont, [30]=0 (vfb slot), [31]=0
__device__ float g_S[BB * TT * 8];   // per (b,t): {ccl, d, td*24, mask_prev, lb_prev, 0,0,0}
__device__ float g_F[BB];            // per batch: (140-age)*weight*gender

typedef unsigned long long u64;

__device__ __forceinline__ u64 pack2(float x, float y) {
    u64 r; asm("mov.b64 %0, {%1, %2};" : "=l"(r) : "f"(x), "f"(y)); return r;
}
__device__ __forceinline__ float2 unpack2(u64 v) {
    float2 r; asm("mov.b64 {%0, %1}, %2;" : "=f"(r.x), "=f"(r.y) : "l"(v)); return r;
}
__device__ __forceinline__ void ffma2(u64& d, u64 a, u64 b) {
    asm("fma.rn.f32x2 %0, %1, %2, %0;" : "+l"(d) : "l"(a), "l"(b));
}
__device__ __forceinline__ float sqrt_approx(float x) {
    float r; asm("sqrt.approx.f32 %0, %1;" : "=f"(r) : "f"(x)); return r;
}
__device__ __forceinline__ float tanh_approx(float x) {
    float r; asm("tanh.approx.f32 %0, %1;" : "=f"(r) : "f"(x)); return r;
}

// ---------------------------------------------------------------------------
// Kernel 0: per-batch ccl factor (one warp per batch) — hoists the t=0-row
// gender ballot + age/weight loads out of the per-(b,t) kernel (512x redundant).
// ---------------------------------------------------------------------------
__global__ void ccl_kernel(const float* __restrict__ cont,
                           const int* __restrict__ cat)
{
    const int lane = threadIdx.x & 31;
    const int b = blockIdx.x * (blockDim.x >> 5) + (threadIdx.x >> 5);
    if (b >= BB) return;
    const int* c0p = cat + (size_t)b * TT * LL;
    int g1 = __ldg(c0p + lane);
    unsigned bal1 = __ballot_sync(0xffffffffu, g1 == 5);
    int g2 = (lane < 8) ? __ldg(c0p + 32 + lane) : 0;
    unsigned bal2 = __ballot_sync(0xffffffffu, (lane < 8) && (g2 == 5));
    if (lane == 0) {
        int gc = __popc(bal1) + __popc(bal2);
        const float* cr0 = cont + (size_t)b * TT * NCF;
        float age = __ldg(cr0 + 2) * 16.936469f + 58.239251f;
        float wgt = __ldg(cr0 + 21) * 30.519849f + 87.5752f;
        float gender = (float)gc * 0.15f + 0.85f;
        g_F[b] = (140.0f - age) * wgt * gender;
    }
}

// ---------------------------------------------------------------------------
// Kernel 1: warp-cooperative embedding gather + feature staging + scalars.
// One WARP per TWO (b,t) rows: 20 interleaved gather LDGs (higher MLP),
// index loads + scalar tail amortized 2x. 8 lanes share each emb row.
// ---------------------------------------------------------------------------
__global__ void precompute_kernel(
    const float* __restrict__ cont, const int* __restrict__ cat,
    const float* __restrict__ lb, const int* __restrict__ mask,
    const float* __restrict__ dvec, const float* __restrict__ td,
    const float* __restrict__ emb)
{
    const int lane = threadIdx.x & 31;
    const int w = blockIdx.x * (blockDim.x >> 5) + (threadIdx.x >> 5);  // 0..65535
    const int b = w >> 8;            // 256 u's per batch
    const int u = w & 255;
    const int t0 = u * 2;
    const size_t btA = (size_t)b * TT + t0;
    const size_t btB = btA + 1;

    // Lane-parallel index loads for both rows
    const int* cpA = cat + btA * LL;
    const int* cpB = cat + btB * LL;
    int a1 = __ldg(cpA + lane);
    int a2 = (lane < 8) ? __ldg(cpA + 32 + lane) : 0;
    int b1 = __ldg(cpB + lane);
    int b2 = (lane < 8) ? __ldg(cpB + 32 + lane) : 0;

    const int r   = lane >> 3;   // row-group 0..3
    const int col = lane & 7;    // emb column 0..7

    float accA = 0.0f, accB = 0.0f;
#pragma unroll
    for (int p = 0; p < 10; p++) {
        int ia, ib;
        if (p < 8) {
            ia = __shfl_sync(0xffffffffu, a1, p * 4 + r);
            ib = __shfl_sync(0xffffffffu, b1, p * 4 + r);
        } else {
            ia = __shfl_sync(0xffffffffu, a2, (p - 8) * 4 + r);
            ib = __shfl_sync(0xffffffffu, b2, (p - 8) * 4 + r);
        }
        accA += __ldg(emb + (size_t)ia * 8 + col);
        accB += __ldg(emb + (size_t)ib * 8 + col);
    }
    // Combine the 4 row-groups (lanes l, l^8, l^16, l^24 end up identical)
    accA += __shfl_xor_sync(0xffffffffu, accA, 8);
    accA += __shfl_xor_sync(0xffffffffu, accA, 16);
    accB += __shfl_xor_sync(0xffffffffu, accB, 8);
    accB += __shfl_xor_sync(0xffffffffu, accB, 16);

    float* xoA = g_X + btA * 32;
    float* xoB = g_X + btB * 32;
    const float* crA = cont + btA * NCF;
    const float* crB = cont + btB * NCF;
    if (lane < 8)       xoA[lane] = accA;       // lanes 0-7 hold cols 0-7 (A)
    else if (lane < 16) xoB[lane - 8] = accB;   // lanes 8-15 hold cols 0-7 (B)
    if (lane < NCF) {
        xoA[8 + lane] = __ldg(crA + lane);
        xoB[8 + lane] = __ldg(crB + lane);
    }
    if (lane == 22) { xoA[30] = 0.0f; xoA[31] = 0.0f; }
    if (lane == 23) { xoB[30] = 0.0f; xoB[31] = 0.0f; }

    // Scalars: lane 0 -> row A, lane 1 -> row B
    if (lane < 2) {
        size_t bt = btA + lane;
        int t = t0 + lane;
        const float* cr = cont + bt * NCF;
        float creat = __ldg(cr + 11) * 1.418099f + 1.314668f;
        float cc = g_F[b] / (72.0f * creat);

        float mp = 0.0f, lp = 0.0f;
        if (t > 0) { mp = (float)__ldg(mask + bt - 1); lp = __ldg(lb + bt - 1); }

        float* so = g_S + bt * 8;
        so[0] = cc;
        so[1] = __ldg(dvec + bt);
        so[2] = __ldg(td + bt) * 24.0f;
        so[3] = mp;
        so[4] = lp;
    }
}

// ---------------------------------------------------------------------------
// Kernel 2: pipelined GRU + PK recurrence — EXACT R15/R12 form (best: 296.7us).
// 128 blocks (<=1/SM), 256 threads (8 warps), 2 batch elements per block:
//   tid 0..191  : GEMV workers (k-packed f32x2 weight row in regs, both
//                 batches). Overlap phase: do_acc(t+1) THEN publish(t+1)
//                 (vfb deferred to gates via w30_sh -> publish needs no vfb).
//   warps 0-3   : also run the gate math (tanh.approx) in the G phase.
//   warp 6 / 7  : x staging (G phase) + eta reduction + shortened PK chain
//                 (overlap phase) for batch 0 / 1.
// Per step: S1 | G: gates + x STS/LDG | S2 | OV: acc+publish // eta+PK.
// ---------------------------------------------------------------------------
__global__ void __launch_bounds__(256, 1) rnn_kernel(
    const float* __restrict__ Wih, const float* __restrict__ Whh,
    const float* __restrict__ bih, const float* __restrict__ bhh,
    const float* __restrict__ Wout, const float* __restrict__ bout,
    float* __restrict__ out)
{
    __shared__ __align__(16) float x_sh[2][32];
    __shared__ __align__(16) float h_sh[2][64];
    __shared__ float gsum_sh[2][128];   // r rows 0-63, z rows 64-127 (gi+gh fused)
    __shared__ float gin_sh[2][64];     // n rows: gi part
    __shared__ float ghn_sh[2][64];     // n rows: gh part
    __shared__ float w30_sh[192];
    __shared__ float vfb_sh[2];
    __shared__ __align__(16) float s_sh[2][TT * 8];  // 32 KB: all PK scalars

    const int tid  = threadIdx.x;
    const int lane = tid & 31;
    const int wid  = tid >> 5;
    const int b0   = blockIdx.x * 2;

    // ---- One-time preload of g_S rows for both batches (contiguous 8192 f) ----
    {
        const float4* src = reinterpret_cast<const float4*>(g_S + (size_t)b0 * TT * 8);
        float4* dst = reinterpret_cast<float4*>(&s_sh[0][0]);
#pragma unroll
        for (int j = 0; j < 8; j++)
            dst[tid + 256 * j] = __ldg(src + tid + 256 * j);
    }

    // Per-thread weights (k-packed pairs)
    u64 wihq[16], whhq[32];
    float bi = 0.0f, bh = 0.0f;
    float wo[8], bo[4];

    if (tid < 192) {
        float tw[32];
#pragma unroll
        for (int k = 0; k < 31; k++) tw[k] = __ldg(Wih + tid * 31 + k);
        w30_sh[tid] = tw[30];
        tw[30] = 0.0f;   // vfb column deferred to gates
        tw[31] = 0.0f;
#pragma unroll
        for (int p = 0; p < 16; p++) wihq[p] = pack2(tw[2 * p], tw[2 * p + 1]);
        float th[64];
#pragma unroll
        for (int k = 0; k < 64; k++) th[k] = __ldg(Whh + tid * 64 + k);
#pragma unroll
        for (int p = 0; p < 32; p++) whhq[p] = pack2(th[2 * p], th[2 * p + 1]);
        bi = __ldg(bih + tid);
        bh = __ldg(bhh + tid);
    } else {
#pragma unroll
        for (int o = 0; o < 4; o++) {
            wo[2 * o]     = __ldg(Wout + o * 64 + lane);
            wo[2 * o + 1] = __ldg(Wout + o * 64 + 32 + lane);
            bo[o] = __ldg(bout + o);
        }
    }

    // GEMV accumulators for both batches
    u64 AX0[2], AX1[2], AH0[2], AH1[2], AH2[2], AH3[2];

    auto do_acc = [&]() {
#pragma unroll
        for (int m = 0; m < 2; m++) {
            u64 a0 = 0ull, a1 = 0ull, c0 = 0ull, c1 = 0ull, c2 = 0ull, c3 = 0ull;
            const ulonglong2* xq = reinterpret_cast<const ulonglong2*>(&x_sh[m][0]);
#pragma unroll
            for (int c = 0; c < 8; c++) {
                ulonglong2 v = xq[c];
                ffma2(a0, wihq[2 * c],     v.x);
                ffma2(a1, wihq[2 * c + 1], v.y);
            }
            const ulonglong2* hq = reinterpret_cast<const ulonglong2*>(&h_sh[m][0]);
#pragma unroll
            for (int c = 0; c < 16; c += 4) {
                ulonglong2 v0 = hq[c], v1 = hq[c + 1], v2 = hq[c + 2], v3 = hq[c + 3];
                ffma2(c0, whhq[2 * c],     v0.x);
                ffma2(c0, whhq[2 * c + 1], v0.y);
                ffma2(c1, whhq[2 * c + 2], v1.x);
                ffma2(c1, whhq[2 * c + 3], v1.y);
                ffma2(c2, whhq[2 * c + 4], v2.x);
                ffma2(c2, whhq[2 * c + 5], v2.y);
                ffma2(c3, whhq[2 * c + 6], v3.x);
                ffma2(c3, whhq[2 * c + 7], v3.y);
            }
            AX0[m] = a0; AX1[m] = a1;
            AH0[m] = c0; AH1[m] = c1; AH2[m] = c2; AH3[m] = c3;
        }
    };
    auto publish = [&]() {
#pragma unroll
        for (int m = 0; m < 2; m++) {
            float2 u0 = unpack2(AX0[m]), u1 = unpack2(AX1[m]);
            float xs = ((u0.x + u0.y) + (u1.x + u1.y)) + bi;
            float2 h0 = unpack2(AH0[m]), h1 = unpack2(AH1[m]);
            float2 h2 = unpack2(AH2[m]), h3 = unpack2(AH3[m]);
            float hs = ((h0.x + h0.y) + (h1.x + h1.y)) +
                       ((h2.x + h2.y) + (h3.x + h3.y)) + bh;
            if (tid < 128) gsum_sh[m][tid] = xs + hs;
            else { gin_sh[m][tid - 128] = xs; ghn_sh[m][tid - 128] = hs; }
        }
    };

    // PK carry + x-prefetch register (live only in PK warps)
    float Cv = 0.0f, Dv = 0.0f;
    float4 xreg = make_float4(0.f, 0.f, 0.f, 0.f);
    const int pk_m = wid - 6;
    const bool is_pk_ld = (wid >= 6) && (lane < 8);
    const float4* xsrc = reinterpret_cast<const float4*>(
        g_X + ((size_t)(b0 + (wid >= 6 ? pk_m : 0)) * TT) * 32);

    // ---- Prime: zero h/vfb, x(0) -> smem, x(1) -> PK regs ----
    if (tid < 128) h_sh[tid >> 6][tid & 63] = 0.0f;
    if (tid < 2) vfb_sh[tid] = 0.0f;
    if (tid >= 128 && tid < 144) {
        int j = tid - 128, m = j >> 3, c = j & 7;
        reinterpret_cast<float4*>(&x_sh[m][0])[c] =
            reinterpret_cast<const float4*>(g_X + ((size_t)(b0 + m) * TT) * 32)[c];
    }
    if (is_pk_ld) xreg = __ldg(xsrc + 8 + lane);   // x(1)
    __syncthreads();
    if (tid < 192) { do_acc(); publish(); }        // step-0 sums (h part = 0)

#pragma unroll 1
    for (int t = 0; t < TT; ++t) {
        __syncthreads();  // S1: gsum(t), vfb(t) visible; x_sh reads of OV(t-1) done

        // ---- G: gates(t) on warps 0-3 || x(t+1) staging on PK warps ----
        if (tid < 128) {
            int m = tid >> 6, i = tid & 63;
            float vfb = vfb_sh[m];
            float gr = fmaf(w30_sh[i],      vfb, gsum_sh[m][i]);
            float gz = fmaf(w30_sh[64 + i], vfb, gsum_sh[m][64 + i]);
            float r  = fmaf(tanh_approx(0.5f * gr), 0.5f, 0.5f);   // sigmoid
            float z  = fmaf(tanh_approx(0.5f * gz), 0.5f, 0.5f);
            float gn = fmaf(w30_sh[128 + i], vfb, gin_sh[m][i]) + r * ghn_sh[m][i];
            float n  = tanh_approx(gn);
            h_sh[m][i] = fmaf(1.0f - z, n, z * h_sh[m][i]);
        } else if (is_pk_ld) {
            if ((t + 1) < TT)
                reinterpret_cast<float4*>(&x_sh[pk_m][0])[lane] = xreg;  // x(t+1)
            int tn = (t + 2) < TT ? (t + 2) : (TT - 1);
            xreg = __ldg(xsrc + (size_t)tn * 8 + lane);                  // x(t+2)
        }
        __syncthreads();  // S2: h(t), x(t+1) visible

        // ---- OV: do_acc(t+1)+publish(t+1) (workers) || eta+PK(t) (w6/7) ----
        if (tid < 192) {
            if ((t + 1) < TT) { do_acc(); publish(); }
        } else {
            int m = pk_m;
            float hl = h_sh[m][lane], hh2 = h_sh[m][lane + 32];
            float p0 = fmaf(wo[0], hl, wo[1] * hh2);
            float p1 = fmaf(wo[2], hl, wo[3] * hh2);
            float p2 = fmaf(wo[4], hl, wo[5] * hh2);
            float p3 = fmaf(wo[6], hl, wo[7] * hh2);
#pragma unroll
            for (int off = 16; off; off >>= 1) {
                p0 += __shfl_xor_sync(0xffffffffu, p0, off);
                p1 += __shfl_xor_sync(0xffffffffu, p1, off);
                p2 += __shfl_xor_sync(0xffffffffu, p2, off);
                p3 += __shfl_xor_sync(0xffffffffu, p3, off);
            }
            float e1 = p0 + bo[0];
            float e2 = p1 + bo[1];
            float e3 = p2 + bo[2];
            float e4 = p3 + bo[3];

            const float* srow = &s_sh[m][t * 8];
            float cc = srow[0], dd = srow[1], ttau = srow[2];

            // Shortened PK chain: parallel MUFUs, analytic 1/v1 = exp(-e1)/33.1
            float Ee1  = __expf(e1);
            float Ene1 = __expf(-e1);
            float v1 = 33.1f * Ee1;
            float rcp_v1 = Ene1 * (1.0f / 33.1f);
            float k1 = 0.0396f * cc * __expf(e2);
            float R  = (-6.99f / 48.3f) * __expf(e3);
            float v2 = 48.3f * __expf(e4);
            float k2 = R * v2;
            float Rv1 = R * v1;
            float q   = k1 - k2 - Rv1;
            float delta = sqrt_approx(fmaf(q, q, 4.0f * k1 * Rv1)) * rcp_v1;
            float s  = -q * rcp_v1;
            float lam1 = (s - delta) * 0.5f;
            float lam2 = (s + delta) * 0.5f;
            float kv = k2 * rcp_v1;
            float rr_kv = (1000.0f * rcp_v1) * kv;
            float C1 =  __fdividef(rr_kv, lam1 * delta);
            float C2 = -__fdividef(rr_kv, lam2 * delta);
            float rcp_kv = __fdividef(1.0f, kv);
            float C3 = -(lam1 - R) * rcp_kv;
            float C4 = -(lam2 - R) * rcp_kv;
            float E1a = __expf(lam1 * dd), E1b = __expf(lam1 * (ttau - dd));
            float E2a = __expf(lam2 * dd), E2b = __expf(lam2 * (ttau - dd));
            float Cn = fmaf(Cv + C1, E1a, -C1) * E1b;
            float Dn = fmaf(Dv + C2, E2a, -C2) * E2b;
            float An = Cn * C3 + Dn * C4;
            Cv = Cn; Dv = Dn;

            float mp = srow[8 + 3];
            float lp = srow[8 + 4];
            float vfb_next = fmaf(An, 1.0f - mp, lp * mp);
            if (lane == 0) {
                out[(size_t)(b0 + m) * TT + t] = An;
                if ((t + 1) < TT) vfb_sh[m] = vfb_next;
            }
        }
    }
}

extern "C" void kernel_launch(void* const* d_in, const int* in_sizes, int n_in,
                              void* d_out, int out_size) {
    const float* cont = (const float*)d_in[0];
    const int*   cat  = (const int*)  d_in[1];
    const float* lb   = (const float*)d_in[2];
    const int*   mask = (const int*)  d_in[3];
    const float* dvec = (const float*)d_in[4];
    const float* td   = (const float*)d_in[5];
    const float* emb  = (const float*)d_in[6];
    const float* Wih  = (const float*)d_in[7];
    const float* Whh  = (const float*)d_in[8];
    const float* bih  = (const float*)d_in[9];
    const float* bhh  = (const float*)d_in[10];
    const float* Wout = (const float*)d_in[11];
    const float* bout = (const float*)d_in[12];

    // per-batch ccl factor: 256 warps (8 warps/block)
    ccl_kernel<<<BB / 8, 256>>>(cont, cat);
    // warp per TWO (b,t): 65536 warps, 8 warps/block -> 8192 blocks
    precompute_kernel<<<(BB * TT / 2) / 8, 256>>>(cont, cat, lb, mask, dvec, td, emb);
    rnn_kernel<<<BB / 2, 256>>>(Wih, Whh, bih, bhh, Wout, bout, (float*)d_out);
}